// round 7
// baseline (speedup 1.0000x reference)
#include <cuda_runtime.h>
#include <cuda_fp16.h>
#include <cstdint>

// ============================================================================
// ContrastiveLoss: N=16384, D=256, T=0.07
// loss = mean_i [ log(sum_j exp((c_ij - 1)/T)) + (1 - selfdot_i)/T ]
// R7: fp16 quantization + fp16-accumulate HMMA, with the DIAGONAL exp term
//     substituted exactly from fp32 selfdot (fp16 accum error on c_ii is the
//     only large error; off-diag error ~1.7e-3 in exp arg averages out).
// ============================================================================

#define N_ROWS 16384
#define DIM    256
#define TILE   128
#define NT     (N_ROWS / TILE)   // 128
#define THREADS 256
#define GRID   148
#define TOTAL_TILES (NT * (NT + 1) / 2)   // 8256

#define INV_T      14.285714285714286f
#define EX2_SCALE  20.60992915555662f   // log2(e)/0.07

__device__ __half g_embn[N_ROWS * DIM];   // normalized fp16 rows (512B/row)
__device__ float g_selfdot[N_ROWS];
__device__ float g_rowsum[N_ROWS];

// ---------------------------------------------------------------------------
__device__ __forceinline__ uint32_t smem_u32(const void* p) {
    uint32_t a;
    asm("{ .reg .u64 t; cvta.to.shared.u64 t, %1; cvt.u32.u64 %0, t; }" : "=r"(a) : "l"(p));
    return a;
}

__device__ __forceinline__ float ex2f(float x) {
    float y;
    asm("ex2.approx.ftz.f32 %0, %1;" : "=f"(y) : "f"(x));
    return y;
}

#define SWZ16(row, c16) (((((c16) ^ (row)) & 7) | ((c16) & 24)))

__device__ __forceinline__ void lm4(uint32_t addr, uint32_t r[4]) {
    asm volatile("ldmatrix.sync.aligned.m8n8.x4.shared.b16 {%0,%1,%2,%3}, [%4];"
                 : "=r"(r[0]), "=r"(r[1]), "=r"(r[2]), "=r"(r[3]) : "r"(addr));
}

// fp16 in, fp16 accumulate: D,C are 2x .f16x2 regs
__device__ __forceinline__ void mma16816h(uint32_t c[2], const uint32_t a[4],
                                          uint32_t b0, uint32_t b1) {
    asm volatile(
        "mma.sync.aligned.m16n8k16.row.col.f16.f16.f16.f16 "
        "{%0,%1}, {%2,%3,%4,%5}, {%6,%7}, {%0,%1};"
        : "+r"(c[0]), "+r"(c[1])
        : "r"(a[0]), "r"(a[1]), "r"(a[2]), "r"(a[3]), "r"(b0), "r"(b1));
}

__device__ __forceinline__ void cp_async16(uint32_t dst, uint64_t src) {
    asm volatile("cp.async.cg.shared.global [%0], [%1], 16;" :: "r"(dst), "l"(src) : "memory");
}
__device__ __forceinline__ void cp_commit() {
    asm volatile("cp.async.commit_group;" ::: "memory");
}

// ---------------------------------------------------------------------------
// Kernel 1: normalize rows -> fp16, self-dot of quantized row, zero g_rowsum
// ---------------------------------------------------------------------------
__global__ void __launch_bounds__(256) normalize_kernel(const float* __restrict__ in) {
    int row  = blockIdx.x * 8 + (threadIdx.x >> 5);
    int lane = threadIdx.x & 31;

    const float4* p = reinterpret_cast<const float4*>(in + (size_t)row * DIM);
    float4 a = p[lane];
    float4 b = p[lane + 32];

    float s = a.x*a.x + a.y*a.y + a.z*a.z + a.w*a.w
            + b.x*b.x + b.y*b.y + b.z*b.z + b.w*b.w;
    #pragma unroll
    for (int o = 16; o; o >>= 1) s += __shfl_xor_sync(0xffffffffu, s, o);

    float inv = 1.0f / sqrtf(s);

    __half q[8];
    q[0] = __float2half(a.x * inv); q[1] = __float2half(a.y * inv);
    q[2] = __float2half(a.z * inv); q[3] = __float2half(a.w * inv);
    q[4] = __float2half(b.x * inv); q[5] = __float2half(b.y * inv);
    q[6] = __float2half(b.z * inv); q[7] = __float2half(b.w * inv);

    float sd = 0.f;
    #pragma unroll
    for (int k = 0; k < 8; ++k) { float f = __half2float(q[k]); sd += f * f; }
    #pragma unroll
    for (int o = 16; o; o >>= 1) sd += __shfl_xor_sync(0xffffffffu, sd, o);

    uint2* out = reinterpret_cast<uint2*>(g_embn + (size_t)row * DIM);
    __half2 h01, h23, h45, h67;
    h01.x = q[0]; h01.y = q[1]; h23.x = q[2]; h23.y = q[3];
    h45.x = q[4]; h45.y = q[5]; h67.x = q[6]; h67.y = q[7];
    uint2 u0, u1;
    u0.x = *reinterpret_cast<uint32_t*>(&h01); u0.y = *reinterpret_cast<uint32_t*>(&h23);
    u1.x = *reinterpret_cast<uint32_t*>(&h45); u1.y = *reinterpret_cast<uint32_t*>(&h67);
    out[lane]      = u0;
    out[lane + 32] = u1;

    if (lane == 0) g_selfdot[row] = sd;
    if (lane == 1) g_rowsum[row] = 0.f;
}

// ---------------------------------------------------------------------------
// Kernel 2: upper-triangle fused GEMM + exp + row/col sums (persistent)
// ---------------------------------------------------------------------------
#define SM_A     0
#define SM_B0    65536
#define SM_B1    131072
#define SM_TOTAL 196608

extern __shared__ char dyn_smem[];

__device__ __forceinline__ void stage_tile(uint32_t sdst, uint64_t gsrc, int tid) {
    int c  = tid & 31;
    int r0 = tid >> 5;
    #pragma unroll
    for (int i = 0; i < 16; ++i) {
        int r = r0 + 8 * i;
        uint32_t d = sdst + r * 512 + SWZ16(r, c) * 16;
        cp_async16(d, gsrc + (uint64_t)r * 512 + (uint64_t)c * 16);
    }
}

// one tile's 16 k-steps accumulating into acc; when EPI, exp-drain prev
// (4 f16 values per k-step) into rowsum/cv and zero prev in place.
// DIAG: prev tile is the diagonal tile -> substitute exact diag exps (esd).
template<bool EPI, bool DIAG>
__device__ __forceinline__ void tile_step(
    uint32_t bbuf, const uint32_t aRow[4], const uint32_t bRow[2],
    int lha, int lhb, int sa, int sbw,
    uint32_t acc[4][4][2], uint32_t prev[4][4][2],
    float rowsum[4][2], float cv0[4], float cv1[4],
    int rb, int cb, const float esd[8])
{
    #pragma unroll
    for (int ks = 0; ks < 16; ++ks) {
        int cA = 2 * ks + lha;
        int cB = 2 * ks + lhb;
        uint32_t offA = (uint32_t)((((cA ^ sa) & 7) | (cA & 24)) << 4);
        uint32_t offB = (uint32_t)((((cB ^ sbw) & 7) | (cB & 24)) << 4);

        uint32_t afr[4][4];
        #pragma unroll
        for (int mb = 0; mb < 4; ++mb) lm4(aRow[mb] + offA, afr[mb]);
        uint32_t bfr[2][4];
        #pragma unroll
        for (int n2 = 0; n2 < 2; ++n2) lm4(bbuf + bRow[n2] + offB, bfr[n2]);

        #pragma unroll
        for (int mb = 0; mb < 4; ++mb)
            #pragma unroll
            for (int nb = 0; nb < 4; ++nb)
                mma16816h(acc[mb][nb], afr[mb],
                          bfr[nb >> 1][(nb & 1) * 2], bfr[nb >> 1][(nb & 1) * 2 + 1]);

        if (EPI) {
            const int mb = ks >> 2, nb = ks & 3;
            __half2 h0 = *reinterpret_cast<__half2*>(&prev[mb][nb][0]);
            __half2 h1 = *reinterpret_cast<__half2*>(&prev[mb][nb][1]);
            float e0 = ex2f(fmaf(__low2float(h0),  EX2_SCALE, -EX2_SCALE));
            float e1 = ex2f(fmaf(__high2float(h0), EX2_SCALE, -EX2_SCALE));
            float e2 = ex2f(fmaf(__low2float(h1),  EX2_SCALE, -EX2_SCALE));
            float e3 = ex2f(fmaf(__high2float(h1), EX2_SCALE, -EX2_SCALE));
            if (DIAG) {
                int rbm = rb + mb * 16;   // local row of (e0,e1)
                int cbn = cb + nb * 8;    // local col of (e0,e2)
                if (rbm == cbn)         e0 = esd[2 * mb];
                if (rbm == cbn + 1)     e1 = esd[2 * mb];
                if (rbm + 8 == cbn)     e2 = esd[2 * mb + 1];
                if (rbm + 8 == cbn + 1) e3 = esd[2 * mb + 1];
            }
            rowsum[mb][0] += e0 + e1;
            rowsum[mb][1] += e2 + e3;
            cv0[nb] += e0 + e2;
            cv1[nb] += e1 + e3;
            prev[mb][nb][0] = 0u;
            prev[mb][nb][1] = 0u;
        }
    }
}

// exp-drain an accumulator array (run tail), zeroing it
template<bool DIAG>
__device__ __forceinline__ void drain_acc(uint32_t acc[4][4][2],
                                          float rowsum[4][2], float cv0[4], float cv1[4],
                                          int rb, int cb, const float esd[8]) {
    #pragma unroll
    for (int mb = 0; mb < 4; ++mb)
        #pragma unroll
        for (int nb = 0; nb < 4; ++nb) {
            __half2 h0 = *reinterpret_cast<__half2*>(&acc[mb][nb][0]);
            __half2 h1 = *reinterpret_cast<__half2*>(&acc[mb][nb][1]);
            float e0 = ex2f(fmaf(__low2float(h0),  EX2_SCALE, -EX2_SCALE));
            float e1 = ex2f(fmaf(__high2float(h0), EX2_SCALE, -EX2_SCALE));
            float e2 = ex2f(fmaf(__low2float(h1),  EX2_SCALE, -EX2_SCALE));
            float e3 = ex2f(fmaf(__high2float(h1), EX2_SCALE, -EX2_SCALE));
            if (DIAG) {
                int rbm = rb + mb * 16;
                int cbn = cb + nb * 8;
                if (rbm == cbn)         e0 = esd[2 * mb];
                if (rbm == cbn + 1)     e1 = esd[2 * mb];
                if (rbm + 8 == cbn)     e2 = esd[2 * mb + 1];
                if (rbm + 8 == cbn + 1) e3 = esd[2 * mb + 1];
            }
            rowsum[mb][0] += e0 + e1;
            rowsum[mb][1] += e2 + e3;
            cv0[nb] += e0 + e2;
            cv1[nb] += e1 + e3;
            acc[mb][nb][0] = 0u;
            acc[mb][nb][1] = 0u;
        }
}

__device__ __forceinline__ void flush_cols(float cv0[4], float cv1[4],
                                           int J, int wc, int l) {
    #pragma unroll
    for (int nb = 0; nb < 4; ++nb) {
        float v0 = cv0[nb], v1 = cv1[nb];
        v0 += __shfl_xor_sync(0xffffffffu, v0, 4);
        v1 += __shfl_xor_sync(0xffffffffu, v1, 4);
        v0 += __shfl_xor_sync(0xffffffffu, v0, 8);
        v1 += __shfl_xor_sync(0xffffffffu, v1, 8);
        v0 += __shfl_xor_sync(0xffffffffu, v0, 16);
        v1 += __shfl_xor_sync(0xffffffffu, v1, 16);
        if (l < 4) {
            int col = J * TILE + wc * 32 + nb * 8 + 2 * l;
            atomicAdd(&g_rowsum[col],     v0);
            atomicAdd(&g_rowsum[col + 1], v1);
        }
        cv0[nb] = 0.f; cv1[nb] = 0.f;
    }
}

__device__ __forceinline__ void zero_cv(float cv0[4], float cv1[4]) {
    cv0[0]=cv0[1]=cv0[2]=cv0[3]=0.f;
    cv1[0]=cv1[1]=cv1[2]=cv1[3]=0.f;
}

__global__ void __launch_bounds__(THREADS, 1) contrastive_main_kernel() {
    int bid = blockIdx.x;
    int tid = threadIdx.x;
    int l   = tid & 31;
    int wid = tid >> 5;
    int wr  = wid >> 2;
    int wc  = wid & 3;
    uint32_t sb = smem_u32(dyn_smem);

    uint64_t gbase;
    asm("cvta.to.global.u64 %0, %1;" : "=l"(gbase) : "l"((const void*)g_embn));

    int la  = l & 15;
    int lha = l >> 4;
    int sa  = la & 7;
    int lb  = (l & 7) + ((l >> 4) << 3);
    int lhb = (l >> 3) & 1;
    int sbw = lb & 7;

    // local (within-tile) row/col bases of this thread's fragment elements
    int rb = wr * 64 + (l >> 2);        // + mb*16 (+8 for second half)
    int cb = wc * 32 + 2 * (l & 3);     // + nb*8 (+1 for odd element)

    uint32_t aRow[4], bRow[2];
    #pragma unroll
    for (int mb = 0; mb < 4; ++mb)
        aRow[mb] = sb + SM_A + (uint32_t)(wr * 64 + mb * 16 + la) * 512;
    #pragma unroll
    for (int n2 = 0; n2 < 2; ++n2)
        bRow[n2] = (uint32_t)(wc * 32 + n2 * 16 + lb) * 512;

    uint32_t accE[4][4][2], accO[4][4][2];
    #pragma unroll
    for (int mb = 0; mb < 4; ++mb)
        #pragma unroll
        for (int nb = 0; nb < 4; ++nb) {
            accE[mb][nb][0] = 0u; accE[mb][nb][1] = 0u;
            accO[mb][nb][0] = 0u; accO[mb][nb][1] = 0u;
        }

    float cv0[4] = {0,0,0,0}, cv1[4] = {0,0,0,0};
    float esd[8] = {0,0,0,0,0,0,0,0};

    // persistent scheduler: linearized triangle, paired row order
    int start = (int)(((long long)bid       * TOTAL_TILES) / GRID);
    int end   = (int)(((long long)(bid + 1) * TOTAL_TILES) / GRID);

    int s = 0, I = 0, cum = 0;
    for (;; ++s) {
        I = (s & 1) ? (NT - 1 - (s >> 1)) : (s >> 1);
        int rowlen = NT - I;
        if (cum + rowlen > start) break;
        cum += rowlen;
    }
    int J0  = I + (start - cum);
    int idx = start;

    while (idx < end) {
        int cnt = min(end - idx, NT - J0);
        bool runDiag = (J0 == I);   // diag tile is t=0 of this run if present

        stage_tile(sb + SM_A,  gbase + (uint64_t)I * TILE * 512, tid);
        stage_tile(sb + SM_B0, gbase + (uint64_t)J0 * TILE * 512, tid);
        cp_commit();
        if (cnt > 1) {
            stage_tile(sb + SM_B1, gbase + (uint64_t)(J0 + 1) * TILE * 512, tid);
            cp_commit();
        }

        // exact diagonal exps: exp((selfdot-1)/T) for this thread's 8 rows
        if (runDiag) {
            #pragma unroll
            for (int mb = 0; mb < 4; ++mb) {
                float sd0 = g_selfdot[I * TILE + rb + mb * 16];
                float sd1 = g_selfdot[I * TILE + rb + mb * 16 + 8];
                esd[2 * mb]     = ex2f(fmaf(sd0, EX2_SCALE, -EX2_SCALE));
                esd[2 * mb + 1] = ex2f(fmaf(sd1, EX2_SCALE, -EX2_SCALE));
            }
        }

        float rowsum[4][2];
        #pragma unroll
        for (int mb = 0; mb < 4; ++mb) { rowsum[mb][0] = 0.f; rowsum[mb][1] = 0.f; }

        int Jprev = -1;

        for (int t = 0; t < cnt; ++t) {
            if (t == cnt - 1) asm volatile("cp.async.wait_group 0;" ::: "memory");
            else              asm volatile("cp.async.wait_group 1;" ::: "memory");
            __syncthreads();

            uint32_t bbuf = sb + ((t & 1) ? SM_B1 : SM_B0);

            // ping-pong: even t accumulates into accE (draining accO), odd into accO
            if (t == 0)
                tile_step<false,false>(bbuf, aRow, bRow, lha, lhb, sa, sbw,
                                       accE, accO, rowsum, cv0, cv1, rb, cb, esd);
            else if (t == 1 && runDiag)
                tile_step<true,true>(bbuf, aRow, bRow, lha, lhb, sa, sbw,
                                     accO, accE, rowsum, cv0, cv1, rb, cb, esd);
            else if (t & 1)
                tile_step<true,false>(bbuf, aRow, bRow, lha, lhb, sa, sbw,
                                      accO, accE, rowsum, cv0, cv1, rb, cb, esd);
            else
                tile_step<true,false>(bbuf, aRow, bRow, lha, lhb, sa, sbw,
                                      accE, accO, rowsum, cv0, cv1, rb, cb, esd);
            __syncthreads();

            if (t + 2 < cnt) {
                stage_tile(sb + ((t & 1) ? SM_B1 : SM_B0),
                           gbase + (uint64_t)(J0 + t + 2) * TILE * 512, tid);
                cp_commit();
            }

            // finish prev tile: flush its column sums (diag tile cols discarded)
            if (t > 0) {
                if (Jprev != I) flush_cols(cv0, cv1, Jprev, wc, l);
                else            zero_cv(cv0, cv1);
            }
            Jprev = J0 + t;
        }

        // drain the run's final tile
        {
            uint32_t (*lastAcc)[4][2] = ((cnt - 1) & 1) ? accO : accE;
            if (cnt == 1 && runDiag)
                drain_acc<true>(lastAcc, rowsum, cv0, cv1, rb, cb, esd);
            else
                drain_acc<false>(lastAcc, rowsum, cv0, cv1, rb, cb, esd);
        }
        if (Jprev != I) flush_cols(cv0, cv1, Jprev, wc, l);
        else            zero_cv(cv0, cv1);

        // flush row sums for this run's I block
        #pragma unroll
        for (int mb = 0; mb < 4; ++mb) {
            #pragma unroll
            for (int ss = 0; ss < 2; ++ss) {
                float p = rowsum[mb][ss];
                p += __shfl_xor_sync(0xffffffffu, p, 1);
                p += __shfl_xor_sync(0xffffffffu, p, 2);
                if ((l & 3) == 0) {
                    int row = I * TILE + wr * 64 + mb * 16 + ss * 8 + (l >> 2);
                    atomicAdd(&g_rowsum[row], p);
                }
            }
        }

        idx += cnt;
        ++s;
        I  = (s & 1) ? (NT - 1 - (s >> 1)) : (s >> 1);
        J0 = I;
    }
}

// ---------------------------------------------------------------------------
// Kernel 3: loss_i = log(rowsum_i) + (1 - selfdot_i)/T;  out = mean
// ---------------------------------------------------------------------------
__global__ void __launch_bounds__(1024) finalize_kernel(float* __restrict__ out) {
    int t = threadIdx.x;
    float acc = 0.f;
    #pragma unroll
    for (int i = 0; i < 16; ++i) {
        int r = t + i * 1024;
        acc += logf(g_rowsum[r]) + (1.0f - g_selfdot[r]) * INV_T;
    }
    #pragma unroll
    for (int o = 16; o; o >>= 1) acc += __shfl_xor_sync(0xffffffffu, acc, o);
    __shared__ float red[32];
    if ((t & 31) == 0) red[t >> 5] = acc;
    __syncthreads();
    if (t < 32) {
        float v = red[t];
        #pragma unroll
        for (int o = 16; o; o >>= 1) v += __shfl_xor_sync(0xffffffffu, v, o);
        if (t == 0) out[0] = v * (1.0f / (float)N_ROWS);
    }
}

// ---------------------------------------------------------------------------
extern "C" void kernel_launch(void* const* d_in, const int* in_sizes, int n_in,
                              void* d_out, int out_size) {
    const float* emb = (const float*)d_in[0];
    float* out = (float*)d_out;
    (void)in_sizes; (void)n_in; (void)out_size;

    cudaFuncSetAttribute(contrastive_main_kernel,
                         cudaFuncAttributeMaxDynamicSharedMemorySize, SM_TOTAL);

    normalize_kernel<<<N_ROWS / 8, 256>>>(emb);
    contrastive_main_kernel<<<GRID, THREADS, SM_TOTAL>>>();
    finalize_kernel<<<1, 1024>>>(out);
}

// round 8
// speedup vs baseline: 1.0022x; 1.0022x over previous
#include <cuda_runtime.h>
#include <cuda_fp16.h>
#include <cstdint>

// ============================================================================
// ContrastiveLoss: N=16384, D=256, T=0.07
// loss = mean_i [ log(sum_j exp((c_ij - 1)/T)) + (1 - selfdot_i)/T ]
// R7: fp16 quantization + fp16-accumulate HMMA, with the DIAGONAL exp term
//     substituted exactly from fp32 selfdot (fp16 accum error on c_ii is the
//     only large error; off-diag error ~1.7e-3 in exp arg averages out).
// ============================================================================

#define N_ROWS 16384
#define DIM    256
#define TILE   128
#define NT     (N_ROWS / TILE)   // 128
#define THREADS 256
#define GRID   148
#define TOTAL_TILES (NT * (NT + 1) / 2)   // 8256

#define INV_T      14.285714285714286f
#define EX2_SCALE  20.60992915555662f   // log2(e)/0.07

__device__ __half g_embn[N_ROWS * DIM];   // normalized fp16 rows (512B/row)
__device__ float g_selfdot[N_ROWS];
__device__ float g_rowsum[N_ROWS];

// ---------------------------------------------------------------------------
__device__ __forceinline__ uint32_t smem_u32(const void* p) {
    uint32_t a;
    asm("{ .reg .u64 t; cvta.to.shared.u64 t, %1; cvt.u32.u64 %0, t; }" : "=r"(a) : "l"(p));
    return a;
}

__device__ __forceinline__ float ex2f(float x) {
    float y;
    asm("ex2.approx.ftz.f32 %0, %1;" : "=f"(y) : "f"(x));
    return y;
}

#define SWZ16(row, c16) (((((c16) ^ (row)) & 7) | ((c16) & 24)))

__device__ __forceinline__ void lm4(uint32_t addr, uint32_t r[4]) {
    asm volatile("ldmatrix.sync.aligned.m8n8.x4.shared.b16 {%0,%1,%2,%3}, [%4];"
                 : "=r"(r[0]), "=r"(r[1]), "=r"(r[2]), "=r"(r[3]) : "r"(addr));
}

// fp16 in, fp16 accumulate: D,C are 2x .f16x2 regs
__device__ __forceinline__ void mma16816h(uint32_t c[2], const uint32_t a[4],
                                          uint32_t b0, uint32_t b1) {
    asm volatile(
        "mma.sync.aligned.m16n8k16.row.col.f16.f16.f16.f16 "
        "{%0,%1}, {%2,%3,%4,%5}, {%6,%7}, {%0,%1};"
        : "+r"(c[0]), "+r"(c[1])
        : "r"(a[0]), "r"(a[1]), "r"(a[2]), "r"(a[3]), "r"(b0), "r"(b1));
}

__device__ __forceinline__ void cp_async16(uint32_t dst, uint64_t src) {
    asm volatile("cp.async.cg.shared.global [%0], [%1], 16;" :: "r"(dst), "l"(src) : "memory");
}
__device__ __forceinline__ void cp_commit() {
    asm volatile("cp.async.commit_group;" ::: "memory");
}

// ---------------------------------------------------------------------------
// Kernel 1: normalize rows -> fp16, self-dot of quantized row, zero g_rowsum
// ---------------------------------------------------------------------------
__global__ void __launch_bounds__(256) normalize_kernel(const float* __restrict__ in) {
    int row  = blockIdx.x * 8 + (threadIdx.x >> 5);
    int lane = threadIdx.x & 31;

    const float4* p = reinterpret_cast<const float4*>(in + (size_t)row * DIM);
    float4 a = p[lane];
    float4 b = p[lane + 32];

    float s = a.x*a.x + a.y*a.y + a.z*a.z + a.w*a.w
            + b.x*b.x + b.y*b.y + b.z*b.z + b.w*b.w;
    #pragma unroll
    for (int o = 16; o; o >>= 1) s += __shfl_xor_sync(0xffffffffu, s, o);

    float inv = 1.0f / sqrtf(s);

    __half q[8];
    q[0] = __float2half(a.x * inv); q[1] = __float2half(a.y * inv);
    q[2] = __float2half(a.z * inv); q[3] = __float2half(a.w * inv);
    q[4] = __float2half(b.x * inv); q[5] = __float2half(b.y * inv);
    q[6] = __float2half(b.z * inv); q[7] = __float2half(b.w * inv);

    float sd = 0.f;
    #pragma unroll
    for (int k = 0; k < 8; ++k) { float f = __half2float(q[k]); sd += f * f; }
    #pragma unroll
    for (int o = 16; o; o >>= 1) sd += __shfl_xor_sync(0xffffffffu, sd, o);

    uint2* out = reinterpret_cast<uint2*>(g_embn + (size_t)row * DIM);
    __half2 h01, h23, h45, h67;
    h01.x = q[0]; h01.y = q[1]; h23.x = q[2]; h23.y = q[3];
    h45.x = q[4]; h45.y = q[5]; h67.x = q[6]; h67.y = q[7];
    uint2 u0, u1;
    u0.x = *reinterpret_cast<uint32_t*>(&h01); u0.y = *reinterpret_cast<uint32_t*>(&h23);
    u1.x = *reinterpret_cast<uint32_t*>(&h45); u1.y = *reinterpret_cast<uint32_t*>(&h67);
    out[lane]      = u0;
    out[lane + 32] = u1;

    if (lane == 0) g_selfdot[row] = sd;
    if (lane == 1) g_rowsum[row] = 0.f;
}

// ---------------------------------------------------------------------------
// Kernel 2: upper-triangle fused GEMM + exp + row/col sums (persistent)
// ---------------------------------------------------------------------------
#define SM_A     0
#define SM_B0    65536
#define SM_B1    131072
#define SM_TOTAL 196608

extern __shared__ char dyn_smem[];

__device__ __forceinline__ void stage_tile(uint32_t sdst, uint64_t gsrc, int tid) {
    int c  = tid & 31;
    int r0 = tid >> 5;
    #pragma unroll
    for (int i = 0; i < 16; ++i) {
        int r = r0 + 8 * i;
        uint32_t d = sdst + r * 512 + SWZ16(r, c) * 16;
        cp_async16(d, gsrc + (uint64_t)r * 512 + (uint64_t)c * 16);
    }
}

// one tile's 16 k-steps accumulating into acc; when EPI, exp-drain prev
// (4 f16 values per k-step) into rowsum/cv and zero prev in place.
// DIAG: prev tile is the diagonal tile -> substitute exact diag exps (esd).
template<bool EPI, bool DIAG>
__device__ __forceinline__ void tile_step(
    uint32_t bbuf, const uint32_t aRow[4], const uint32_t bRow[2],
    int lha, int lhb, int sa, int sbw,
    uint32_t acc[4][4][2], uint32_t prev[4][4][2],
    float rowsum[4][2], float cv0[4], float cv1[4],
    int rb, int cb, const float esd[8])
{
    #pragma unroll
    for (int ks = 0; ks < 16; ++ks) {
        int cA = 2 * ks + lha;
        int cB = 2 * ks + lhb;
        uint32_t offA = (uint32_t)((((cA ^ sa) & 7) | (cA & 24)) << 4);
        uint32_t offB = (uint32_t)((((cB ^ sbw) & 7) | (cB & 24)) << 4);

        uint32_t afr[4][4];
        #pragma unroll
        for (int mb = 0; mb < 4; ++mb) lm4(aRow[mb] + offA, afr[mb]);
        uint32_t bfr[2][4];
        #pragma unroll
        for (int n2 = 0; n2 < 2; ++n2) lm4(bbuf + bRow[n2] + offB, bfr[n2]);

        #pragma unroll
        for (int mb = 0; mb < 4; ++mb)
            #pragma unroll
            for (int nb = 0; nb < 4; ++nb)
                mma16816h(acc[mb][nb], afr[mb],
                          bfr[nb >> 1][(nb & 1) * 2], bfr[nb >> 1][(nb & 1) * 2 + 1]);

        if (EPI) {
            const int mb = ks >> 2, nb = ks & 3;
            __half2 h0 = *reinterpret_cast<__half2*>(&prev[mb][nb][0]);
            __half2 h1 = *reinterpret_cast<__half2*>(&prev[mb][nb][1]);
            float e0 = ex2f(fmaf(__low2float(h0),  EX2_SCALE, -EX2_SCALE));
            float e1 = ex2f(fmaf(__high2float(h0), EX2_SCALE, -EX2_SCALE));
            float e2 = ex2f(fmaf(__low2float(h1),  EX2_SCALE, -EX2_SCALE));
            float e3 = ex2f(fmaf(__high2float(h1), EX2_SCALE, -EX2_SCALE));
            if (DIAG) {
                int rbm = rb + mb * 16;   // local row of (e0,e1)
                int cbn = cb + nb * 8;    // local col of (e0,e2)
                if (rbm == cbn)         e0 = esd[2 * mb];
                if (rbm == cbn + 1)     e1 = esd[2 * mb];
                if (rbm + 8 == cbn)     e2 = esd[2 * mb + 1];
                if (rbm + 8 == cbn + 1) e3 = esd[2 * mb + 1];
            }
            rowsum[mb][0] += e0 + e1;
            rowsum[mb][1] += e2 + e3;
            cv0[nb] += e0 + e2;
            cv1[nb] += e1 + e3;
            prev[mb][nb][0] = 0u;
            prev[mb][nb][1] = 0u;
        }
    }
}

// exp-drain an accumulator array (run tail), zeroing it
template<bool DIAG>
__device__ __forceinline__ void drain_acc(uint32_t acc[4][4][2],
                                          float rowsum[4][2], float cv0[4], float cv1[4],
                                          int rb, int cb, const float esd[8]) {
    #pragma unroll
    for (int mb = 0; mb < 4; ++mb)
        #pragma unroll
        for (int nb = 0; nb < 4; ++nb) {
            __half2 h0 = *reinterpret_cast<__half2*>(&acc[mb][nb][0]);
            __half2 h1 = *reinterpret_cast<__half2*>(&acc[mb][nb][1]);
            float e0 = ex2f(fmaf(__low2float(h0),  EX2_SCALE, -EX2_SCALE));
            float e1 = ex2f(fmaf(__high2float(h0), EX2_SCALE, -EX2_SCALE));
            float e2 = ex2f(fmaf(__low2float(h1),  EX2_SCALE, -EX2_SCALE));
            float e3 = ex2f(fmaf(__high2float(h1), EX2_SCALE, -EX2_SCALE));
            if (DIAG) {
                int rbm = rb + mb * 16;
                int cbn = cb + nb * 8;
                if (rbm == cbn)         e0 = esd[2 * mb];
                if (rbm == cbn + 1)     e1 = esd[2 * mb];
                if (rbm + 8 == cbn)     e2 = esd[2 * mb + 1];
                if (rbm + 8 == cbn + 1) e3 = esd[2 * mb + 1];
            }
            rowsum[mb][0] += e0 + e1;
            rowsum[mb][1] += e2 + e3;
            cv0[nb] += e0 + e2;
            cv1[nb] += e1 + e3;
            acc[mb][nb][0] = 0u;
            acc[mb][nb][1] = 0u;
        }
}

__device__ __forceinline__ void flush_cols(float cv0[4], float cv1[4],
                                           int J, int wc, int l) {
    #pragma unroll
    for (int nb = 0; nb < 4; ++nb) {
        float v0 = cv0[nb], v1 = cv1[nb];
        v0 += __shfl_xor_sync(0xffffffffu, v0, 4);
        v1 += __shfl_xor_sync(0xffffffffu, v1, 4);
        v0 += __shfl_xor_sync(0xffffffffu, v0, 8);
        v1 += __shfl_xor_sync(0xffffffffu, v1, 8);
        v0 += __shfl_xor_sync(0xffffffffu, v0, 16);
        v1 += __shfl_xor_sync(0xffffffffu, v1, 16);
        if (l < 4) {
            int col = J * TILE + wc * 32 + nb * 8 + 2 * l;
            atomicAdd(&g_rowsum[col],     v0);
            atomicAdd(&g_rowsum[col + 1], v1);
        }
        cv0[nb] = 0.f; cv1[nb] = 0.f;
    }
}

__device__ __forceinline__ void zero_cv(float cv0[4], float cv1[4]) {
    cv0[0]=cv0[1]=cv0[2]=cv0[3]=0.f;
    cv1[0]=cv1[1]=cv1[2]=cv1[3]=0.f;
}

__global__ void __launch_bounds__(THREADS, 1) contrastive_main_kernel() {
    int bid = blockIdx.x;
    int tid = threadIdx.x;
    int l   = tid & 31;
    int wid = tid >> 5;
    int wr  = wid >> 2;
    int wc  = wid & 3;
    uint32_t sb = smem_u32(dyn_smem);

    uint64_t gbase;
    asm("cvta.to.global.u64 %0, %1;" : "=l"(gbase) : "l"((const void*)g_embn));

    int la  = l & 15;
    int lha = l >> 4;
    int sa  = la & 7;
    int lb  = (l & 7) + ((l >> 4) << 3);
    int lhb = (l >> 3) & 1;
    int sbw = lb & 7;

    // local (within-tile) row/col bases of this thread's fragment elements
    int rb = wr * 64 + (l >> 2);        // + mb*16 (+8 for second half)
    int cb = wc * 32 + 2 * (l & 3);     // + nb*8 (+1 for odd element)

    uint32_t aRow[4], bRow[2];
    #pragma unroll
    for (int mb = 0; mb < 4; ++mb)
        aRow[mb] = sb + SM_A + (uint32_t)(wr * 64 + mb * 16 + la) * 512;
    #pragma unroll
    for (int n2 = 0; n2 < 2; ++n2)
        bRow[n2] = (uint32_t)(wc * 32 + n2 * 16 + lb) * 512;

    uint32_t accE[4][4][2], accO[4][4][2];
    #pragma unroll
    for (int mb = 0; mb < 4; ++mb)
        #pragma unroll
        for (int nb = 0; nb < 4; ++nb) {
            accE[mb][nb][0] = 0u; accE[mb][nb][1] = 0u;
            accO[mb][nb][0] = 0u; accO[mb][nb][1] = 0u;
        }

    float cv0[4] = {0,0,0,0}, cv1[4] = {0,0,0,0};
    float esd[8] = {0,0,0,0,0,0,0,0};

    // persistent scheduler: linearized triangle, paired row order
    int start = (int)(((long long)bid       * TOTAL_TILES) / GRID);
    int end   = (int)(((long long)(bid + 1) * TOTAL_TILES) / GRID);

    int s = 0, I = 0, cum = 0;
    for (;; ++s) {
        I = (s & 1) ? (NT - 1 - (s >> 1)) : (s >> 1);
        int rowlen = NT - I;
        if (cum + rowlen > start) break;
        cum += rowlen;
    }
    int J0  = I + (start - cum);
    int idx = start;

    while (idx < end) {
        int cnt = min(end - idx, NT - J0);
        bool runDiag = (J0 == I);   // diag tile is t=0 of this run if present

        stage_tile(sb + SM_A,  gbase + (uint64_t)I * TILE * 512, tid);
        stage_tile(sb + SM_B0, gbase + (uint64_t)J0 * TILE * 512, tid);
        cp_commit();
        if (cnt > 1) {
            stage_tile(sb + SM_B1, gbase + (uint64_t)(J0 + 1) * TILE * 512, tid);
            cp_commit();
        }

        // exact diagonal exps: exp((selfdot-1)/T) for this thread's 8 rows
        if (runDiag) {
            #pragma unroll
            for (int mb = 0; mb < 4; ++mb) {
                float sd0 = g_selfdot[I * TILE + rb + mb * 16];
                float sd1 = g_selfdot[I * TILE + rb + mb * 16 + 8];
                esd[2 * mb]     = ex2f(fmaf(sd0, EX2_SCALE, -EX2_SCALE));
                esd[2 * mb + 1] = ex2f(fmaf(sd1, EX2_SCALE, -EX2_SCALE));
            }
        }

        float rowsum[4][2];
        #pragma unroll
        for (int mb = 0; mb < 4; ++mb) { rowsum[mb][0] = 0.f; rowsum[mb][1] = 0.f; }

        int Jprev = -1;

        for (int t = 0; t < cnt; ++t) {
            if (t == cnt - 1) asm volatile("cp.async.wait_group 0;" ::: "memory");
            else              asm volatile("cp.async.wait_group 1;" ::: "memory");
            __syncthreads();

            uint32_t bbuf = sb + ((t & 1) ? SM_B1 : SM_B0);

            // ping-pong: even t accumulates into accE (draining accO), odd into accO
            if (t == 0)
                tile_step<false,false>(bbuf, aRow, bRow, lha, lhb, sa, sbw,
                                       accE, accO, rowsum, cv0, cv1, rb, cb, esd);
            else if (t == 1 && runDiag)
                tile_step<true,true>(bbuf, aRow, bRow, lha, lhb, sa, sbw,
                                     accO, accE, rowsum, cv0, cv1, rb, cb, esd);
            else if (t & 1)
                tile_step<true,false>(bbuf, aRow, bRow, lha, lhb, sa, sbw,
                                      accO, accE, rowsum, cv0, cv1, rb, cb, esd);
            else
                tile_step<true,false>(bbuf, aRow, bRow, lha, lhb, sa, sbw,
                                      accE, accO, rowsum, cv0, cv1, rb, cb, esd);
            __syncthreads();

            if (t + 2 < cnt) {
                stage_tile(sb + ((t & 1) ? SM_B1 : SM_B0),
                           gbase + (uint64_t)(J0 + t + 2) * TILE * 512, tid);
                cp_commit();
            }

            // finish prev tile: flush its column sums (diag tile cols discarded)
            if (t > 0) {
                if (Jprev != I) flush_cols(cv0, cv1, Jprev, wc, l);
                else            zero_cv(cv0, cv1);
            }
            Jprev = J0 + t;
        }

        // drain the run's final tile
        {
            uint32_t (*lastAcc)[4][2] = ((cnt - 1) & 1) ? accO : accE;
            if (cnt == 1 && runDiag)
                drain_acc<true>(lastAcc, rowsum, cv0, cv1, rb, cb, esd);
            else
                drain_acc<false>(lastAcc, rowsum, cv0, cv1, rb, cb, esd);
        }
        if (Jprev != I) flush_cols(cv0, cv1, Jprev, wc, l);
        else            zero_cv(cv0, cv1);

        // flush row sums for this run's I block
        #pragma unroll
        for (int mb = 0; mb < 4; ++mb) {
            #pragma unroll
            for (int ss = 0; ss < 2; ++ss) {
                float p = rowsum[mb][ss];
                p += __shfl_xor_sync(0xffffffffu, p, 1);
                p += __shfl_xor_sync(0xffffffffu, p, 2);
                if ((l & 3) == 0) {
                    int row = I * TILE + wr * 64 + mb * 16 + ss * 8 + (l >> 2);
                    atomicAdd(&g_rowsum[row], p);
                }
            }
        }

        idx += cnt;
        ++s;
        I  = (s & 1) ? (NT - 1 - (s >> 1)) : (s >> 1);
        J0 = I;
    }
}

// ---------------------------------------------------------------------------
// Kernel 3: loss_i = log(rowsum_i) + (1 - selfdot_i)/T;  out = mean
// ---------------------------------------------------------------------------
__global__ void __launch_bounds__(1024) finalize_kernel(float* __restrict__ out) {
    int t = threadIdx.x;
    float acc = 0.f;
    #pragma unroll
    for (int i = 0; i < 16; ++i) {
        int r = t + i * 1024;
        acc += logf(g_rowsum[r]) + (1.0f - g_selfdot[r]) * INV_T;
    }
    #pragma unroll
    for (int o = 16; o; o >>= 1) acc += __shfl_xor_sync(0xffffffffu, acc, o);
    __shared__ float red[32];
    if ((t & 31) == 0) red[t >> 5] = acc;
    __syncthreads();
    if (t < 32) {
        float v = red[t];
        #pragma unroll
        for (int o = 16; o; o >>= 1) v += __shfl_xor_sync(0xffffffffu, v, o);
        if (t == 0) out[0] = v * (1.0f / (float)N_ROWS);
    }
}

// ---------------------------------------------------------------------------
extern "C" void kernel_launch(void* const* d_in, const int* in_sizes, int n_in,
                              void* d_out, int out_size) {
    const float* emb = (const float*)d_in[0];
    float* out = (float*)d_out;
    (void)in_sizes; (void)n_in; (void)out_size;

    cudaFuncSetAttribute(contrastive_main_kernel,
                         cudaFuncAttributeMaxDynamicSharedMemorySize, SM_TOTAL);

    normalize_kernel<<<N_ROWS / 8, 256>>>(emb);
    contrastive_main_kernel<<<GRID, THREADS, SM_TOTAL>>>();
    finalize_kernel<<<1, 1024>>>(out);
}